// round 8
// baseline (speedup 1.0000x reference)
#include <cuda_runtime.h>
#include <math.h>

#define NB 64
#define CC 64
#define TT 256
#define VV 25
#define SS 3
#define II 16

typedef unsigned long long ull;

// ---------------- device scratch ----------------
__device__ float g_A1 [NB*SS*VV*VV];
__device__ float g_Ai [NB*SS*VV*VV];
__device__ float g_y0 [NB*CC*TT*VV];   // ~105MB
__device__ float g_ST [NB*CC*VV];
__device__ float g_SVw[NB*CC*TT];
__device__ float g_gs [NB*VV];
__device__ float g_gt [NB*TT];
__device__ float g_gc [NB*CC];

__device__ __forceinline__ float sigm(float x) { return 1.0f / (1.0f + expf(-x)); }

// packed fp32x2 helpers
__device__ __forceinline__ ull pack2(float f) {
    ull r;
    asm("mov.b64 %0, {%1, %1};" : "=l"(r) : "r"(__float_as_uint(f)));
    return r;
}
__device__ __forceinline__ void fma2(ull& d, ull a, ull b) {
    asm("fma.rn.f32x2 %0, %1, %2, %0;" : "+l"(d) : "l"(a), "l"(b));
}
__device__ __forceinline__ float2 unpack2(ull p) {
    unsigned lo, hi;
    asm("mov.b64 {%0, %1}, %2;" : "=r"(lo), "=r"(hi) : "l"(p));
    return make_float2(__uint_as_float(lo), __uint_as_float(hi));
}

// ---------------- K0 ----------------
__global__ void k0_zero() {
    const int tot = NB*SS*VV*VV + NB*CC*VV;
    for (int i = blockIdx.x*blockDim.x + threadIdx.x; i < tot; i += gridDim.x*blockDim.x) {
        if (i < NB*SS*VV*VV) g_A1[i] = 0.f;
        else                 g_ST[i - NB*SS*VV*VV] = 0.f;
    }
}

// ---------------- K1: embeddings + partial A1 ----------------
// grid (8, 64), 256 threads, dyn smem 67968 B
__global__ __launch_bounds__(256) void k1_emb_adj(
    const float* __restrict__ x,  const float* __restrict__ Wa, const float* __restrict__ ba,
    const float* __restrict__ Wb, const float* __restrict__ bb)
{
    extern __shared__ float sm1[];
    float* Xs  = sm1;             // 6400: [c][t*25+v] flat
    float* Es  = sm1 + 6400;      // 3584: 32 rows x 112, flat [0,100) per row
    float* Wt3 = sm1 + 9984;      // 6912: [s][c][36-pad j]  (j: 0..15 a, 16..31 b)
    float* bs3 = sm1 + 16896;     // 96:   [s][32]

    const int tid = threadIdx.x;
    const int n   = blockIdx.y;

    // stage ALL weights once (transposed for vector loads)
    for (int i = tid; i < 6144; i += 256) {
        int s = i >> 11, r = i & 2047, j = r >> 6, c = r & 63;
        float w = (j < 16) ? Wa[(s*16 + j)*64 + c] : Wb[(s*16 + (j-16))*64 + c];
        Wt3[(s*64 + c)*36 + j] = w;
    }
    if (tid < 96) {
        int s = tid / 32, j = tid % 32;
        bs3[tid] = (j < 16) ? ba[s*16 + j] : bb[s*16 + (j-16)];
    }

    float accA0[SS], accA1[SS], accA2[SS], accA3[SS];
    #pragma unroll
    for (int s = 0; s < SS; ++s) { accA0[s]=0.f; accA1[s]=0.f; accA2[s]=0.f; accA3[s]=0.f; }
    const bool hasA = tid < 175;
    const int  vA = tid / 7, w4A = tid % 7;
    const bool hasE = tid < 200;
    const int  jg = tid / 25, q = tid % 25;

    __syncthreads();

    for (int sub = 0; sub < 8; ++sub) {
        const int tile = blockIdx.x * 8 + sub;
        __syncthreads();   // prev readers of Xs/Es done
        {
            const float4* xg = (const float4*)x;
            float4* Xs4 = (float4*)Xs;
            for (int i = tid; i < 1600; i += 256) {
                int c = i / 25, qq = i - c*25;
                Xs4[c*25 + qq] = xg[(n*64 + c)*1600 + tile*25 + qq];
            }
        }
        __syncthreads();

        for (int s = 0; s < SS; ++s) {
            // embeddings: 4-j blocking, vector W loads, FFMA2
            if (hasE) {
                const ulonglong2* Xs2 = (const ulonglong2*)Xs;
                const float* wb_ = Wt3 + s*64*36;
                const float* bsp = bs3 + s*32 + jg*4;
                ull a0x = pack2(bsp[0]), a0y = a0x;
                ull a1x = pack2(bsp[1]), a1y = a1x;
                ull a2x = pack2(bsp[2]), a2y = a2x;
                ull a3x = pack2(bsp[3]), a3y = a3x;
                #pragma unroll 8
                for (int c = 0; c < 64; ++c) {
                    float4 wv = *(const float4*)(wb_ + c*36 + jg*4);
                    ulonglong2 xv = Xs2[c*25 + q];
                    ull w0 = pack2(wv.x), w1 = pack2(wv.y), w2 = pack2(wv.z), w3 = pack2(wv.w);
                    fma2(a0x, w0, xv.x); fma2(a0y, w0, xv.y);
                    fma2(a1x, w1, xv.x); fma2(a1y, w1, xv.y);
                    fma2(a2x, w2, xv.x); fma2(a2y, w2, xv.y);
                    fma2(a3x, w3, xv.x); fma2(a3y, w3, xv.y);
                }
                ulonglong2* Es2 = (ulonglong2*)Es;
                Es2[(jg*4+0)*28 + q] = make_ulonglong2(a0x, a0y);
                Es2[(jg*4+1)*28 + q] = make_ulonglong2(a1x, a1y);
                Es2[(jg*4+2)*28 + q] = make_ulonglong2(a2x, a2y);
                Es2[(jg*4+3)*28 + q] = make_ulonglong2(a3x, a3y);
            }
            __syncthreads();

            // A1 partial (flat within-row addressing t*25+v)
            if (hasA) {
                float c0 = accA0[s], c1 = accA1[s], c2 = accA2[s], c3 = accA3[s];
                #pragma unroll 4
                for (int j = 0; j < 16; ++j) {
                    #pragma unroll
                    for (int t = 0; t < 4; ++t) {
                        float av = Es[j*112 + t*25 + vA];
                        const float* br = &Es[(16+j)*112 + t*25 + w4A*4];
                        c0 += av*br[0]; c1 += av*br[1]; c2 += av*br[2]; c3 += av*br[3];
                    }
                }
                accA0[s] = c0; accA1[s] = c1; accA2[s] = c2; accA3[s] = c3;
            }
            __syncthreads();
        }
    }

    if (hasA) {
        #pragma unroll
        for (int s = 0; s < SS; ++s) {
            float* dst = &g_A1[((n*SS + s)*VV + vA)*VV];
            float vals[4] = {accA0[s], accA1[s], accA2[s], accA3[s]};
            #pragma unroll
            for (int k = 0; k < 4; ++k) {
                int w = w4A*4 + k;
                if (w < VV) atomicAdd(&dst[w], vals[k]);
            }
        }
    }
}

// ---------------- K2 ----------------
__global__ void k2_adj(const float* __restrict__ PA, const float* __restrict__ alpha) {
    const float al = alpha[0];
    const int tot = NB*SS*VV*VV;
    for (int i = blockIdx.x*blockDim.x + threadIdx.x; i < tot; i += gridDim.x*blockDim.x)
        g_Ai[i] = PA[i % (SS*VV*VV)] + al * tanhf(g_A1[i] * (1.0f/4096.0f));
}

// ---------------- K3: main fused compute ----------------
// grid (64, 64), 128 threads, dyn smem 66304 B
__global__ __launch_bounds__(128, 3) void k3_main(
    const float* __restrict__ x,  const float* __restrict__ Wd, const float* __restrict__ bd,
    const float* __restrict__ gamma, const float* __restrict__ beta)
{
    extern __shared__ float sm[];
    float* Zs  = sm;                  // 7168: [64][112]
    float* Ais = sm + 7168;           // 704:  [25][28]
    ull*   Wt2 = (ull*)(sm + 7872);   // 4352 ull: [c][68-pad o], each = pack2(Wd[s][o][c])

    const int tid  = threadIdx.x;
    const int n    = blockIdx.y;
    const int tile = blockIdx.x;               // t0 = tile*4
    // Z-stage mapping
    const int cz = tid >> 2, tz = tid & 3;
    // GEMM mapping (warp-uniform wh)
    const int wh = tid >> 6;                   // 0: w[0,16), 1: w[16,28)
    const int og = (tid >> 2) & 15;
    const int tg = tid & 3;
    const int ob = og * 4;

    // X rows in registers (Z-stage input)
    float xr0[25], xr1[25];
    {
        const float* xp0 = x + (n*64 + cz)*6400 + (tile*4 + tz)*25;
        const float* xp1 = xp0 + 32*6400;
        #pragma unroll
        for (int v = 0; v < 25; ++v) { xr0[v] = xp0[v]; xr1[v] = xp1[v]; }
    }

    if (tid < 25) { Ais[tid*28+25] = 0.f; Ais[tid*28+26] = 0.f; Ais[tid*28+27] = 0.f; }

    ull acc0[8], acc1[8], acc2[8], acc3[8];
    #pragma unroll
    for (int k = 0; k < 8; ++k) { acc0[k]=0ULL; acc1[k]=0ULL; acc2[k]=0ULL; acc3[k]=0ULL; }

    for (int s = 0; s < SS; ++s) {
        __syncthreads();
        for (int i = tid; i < 625; i += 128) Ais[(i/25)*28 + (i%25)] = g_Ai[(n*SS + s)*625 + i];
        for (int i = tid; i < 4096; i += 128) {
            int o = i >> 6, c = i & 63;
            Wt2[c*68 + o] = pack2(Wd[s*4096 + i]);
        }
        __syncthreads();

        // Z[c][t][w] = sum_v X[c][t][v] * Ai[v][w]
        {
            const ulonglong2* Ai2 = (const ulonglong2*)Ais;
            #pragma unroll
            for (int r = 0; r < 2; ++r) {
                const float* xr = r ? xr1 : xr0;
                const int c = cz + r*32;
                ull z[14];
                #pragma unroll
                for (int k = 0; k < 14; ++k) z[k] = 0ULL;
                #pragma unroll
                for (int v = 0; v < 25; ++v) {
                    ull xv = pack2(xr[v]);
                    #pragma unroll
                    for (int w4 = 0; w4 < 7; ++w4) {
                        ulonglong2 a = Ai2[v*7 + w4];
                        fma2(z[2*w4], xv, a.x); fma2(z[2*w4+1], xv, a.y);
                    }
                }
                ulonglong2* zd = (ulonglong2*)(Zs + c*112 + tz*28);
                #pragma unroll
                for (int w4 = 0; w4 < 7; ++w4) zd[w4] = make_ulonglong2(z[2*w4], z[2*w4+1]);
            }
        }
        __syncthreads();

        // Y[o][t][w] += sum_c W[o][c] * Z[c][t][w] — 4-o micro-tile, pre-packed W, no pack2
        if (wh == 0) {
            #pragma unroll 2
            for (int c = 0; c < 64; ++c) {
                const ulonglong2* wp = (const ulonglong2*)(Wt2 + c*68 + ob);
                ulonglong2 wab = wp[0], wcd = wp[1];
                const ulonglong2* zp = (const ulonglong2*)(Zs + c*112 + tg*28);
                ulonglong2 q0 = zp[0], q1 = zp[1], q2 = zp[2], q3 = zp[3];
                fma2(acc0[0], wab.x, q0.x); fma2(acc0[1], wab.x, q0.y);
                fma2(acc0[2], wab.x, q1.x); fma2(acc0[3], wab.x, q1.y);
                fma2(acc0[4], wab.x, q2.x); fma2(acc0[5], wab.x, q2.y);
                fma2(acc0[6], wab.x, q3.x); fma2(acc0[7], wab.x, q3.y);
                fma2(acc1[0], wab.y, q0.x); fma2(acc1[1], wab.y, q0.y);
                fma2(acc1[2], wab.y, q1.x); fma2(acc1[3], wab.y, q1.y);
                fma2(acc1[4], wab.y, q2.x); fma2(acc1[5], wab.y, q2.y);
                fma2(acc1[6], wab.y, q3.x); fma2(acc1[7], wab.y, q3.y);
                fma2(acc2[0], wcd.x, q0.x); fma2(acc2[1], wcd.x, q0.y);
                fma2(acc2[2], wcd.x, q1.x); fma2(acc2[3], wcd.x, q1.y);
                fma2(acc2[4], wcd.x, q2.x); fma2(acc2[5], wcd.x, q2.y);
                fma2(acc2[6], wcd.x, q3.x); fma2(acc2[7], wcd.x, q3.y);
                fma2(acc3[0], wcd.y, q0.x); fma2(acc3[1], wcd.y, q0.y);
                fma2(acc3[2], wcd.y, q1.x); fma2(acc3[3], wcd.y, q1.y);
                fma2(acc3[4], wcd.y, q2.x); fma2(acc3[5], wcd.y, q2.y);
                fma2(acc3[6], wcd.y, q3.x); fma2(acc3[7], wcd.y, q3.y);
            }
        } else {
            #pragma unroll 2
            for (int c = 0; c < 64; ++c) {
                const ulonglong2* wp = (const ulonglong2*)(Wt2 + c*68 + ob);
                ulonglong2 wab = wp[0], wcd = wp[1];
                const ulonglong2* zp = (const ulonglong2*)(Zs + c*112 + tg*28 + 16);
                ulonglong2 q0 = zp[0], q1 = zp[1], q2 = zp[2];
                fma2(acc0[0], wab.x, q0.x); fma2(acc0[1], wab.x, q0.y);
                fma2(acc0[2], wab.x, q1.x); fma2(acc0[3], wab.x, q1.y);
                fma2(acc0[4], wab.x, q2.x); fma2(acc0[5], wab.x, q2.y);
                fma2(acc1[0], wab.y, q0.x); fma2(acc1[1], wab.y, q0.y);
                fma2(acc1[2], wab.y, q1.x); fma2(acc1[3], wab.y, q1.y);
                fma2(acc1[4], wab.y, q2.x); fma2(acc1[5], wab.y, q2.y);
                fma2(acc2[0], wcd.x, q0.x); fma2(acc2[1], wcd.x, q0.y);
                fma2(acc2[2], wcd.x, q1.x); fma2(acc2[3], wcd.x, q1.y);
                fma2(acc2[4], wcd.x, q2.x); fma2(acc2[5], wcd.x, q2.y);
                fma2(acc3[0], wcd.y, q0.x); fma2(acc3[1], wcd.y, q0.y);
                fma2(acc3[2], wcd.y, q1.x); fma2(acc3[3], wcd.y, q1.y);
                fma2(acc3[4], wcd.y, q2.x); fma2(acc3[5], wcd.y, q2.y);
            }
        }
    }
    __syncthreads();   // all Zs reads done

    // epilogue: bias + BN + residual + relu, stage y0 into Zs flat [o][t*25+w]
    {
        const float scl = rsqrtf(1.0f + 1e-5f);
        const int wbase = wh * 16;
        ull* accs[4] = {acc0, acc1, acc2, acc3};
        #pragma unroll
        for (int k = 0; k < 4; ++k) {
            const int o = ob + k;
            const float bsum = bd[o] + bd[64+o] + bd[128+o];
            const float scv  = gamma[o]*scl;
            const float btv  = beta[o];
            const float* xp = x + (n*64 + o)*6400 + (tile*4 + tg)*25 + wbase;
            float* zsp = Zs + o*100 + tg*25 + wbase;
            float yv[16];
            #pragma unroll
            for (int u = 0; u < 8; ++u) {
                float2 f = unpack2(accs[k][u]); yv[2*u] = f.x; yv[2*u+1] = f.y;
            }
            if (wh == 0) {
                #pragma unroll
                for (int j = 0; j < 16; ++j)
                    zsp[j] = fmaxf((yv[j] + bsum)*scv + btv + xp[j], 0.f);
            } else {
                #pragma unroll
                for (int j = 0; j < 9; ++j)
                    zsp[j] = fmaxf((yv[j] + bsum)*scv + btv + xp[j], 0.f);
            }
        }
    }
    __syncthreads();

    {   // coalesced y0 store + ST atomic accumulate
        float4* yg = (float4*)g_y0;
        const float4* Zs4 = (const float4*)Zs;
        for (int i = tid; i < 1600; i += 128) {
            int c = i / 25, qq = i - c*25;
            yg[(n*64 + c)*1600 + tile*25 + qq] = Zs4[c*25 + qq];
        }
        for (int i = tid; i < 1600; i += 128) {
            int c = i / 25, v = i - c*25;
            float ssum = Zs[c*100 + v] + Zs[c*100 + 25 + v]
                       + Zs[c*100 + 50 + v] + Zs[c*100 + 75 + v];
            atomicAdd(&g_ST[n*1600 + i], ssum);
        }
    }
}

// ---------------- K4: spatial gate ----------------
__global__ __launch_bounds__(128) void k4_sgate(const float* __restrict__ Wsa,
                                                const float* __restrict__ bsa)
{
    __shared__ float se[1600];
    __shared__ float wk[1600];
    const int tid = threadIdx.x, n = blockIdx.x;
    for (int i = tid; i < 1600; i += 128) {
        se[i] = g_ST[n*1600 + i] * (1.0f/256.0f);
        wk[i] = Wsa[i];
    }
    __syncthreads();
    if (tid < VV) {
        int v = tid;
        float acc = bsa[0];
        for (int c = 0; c < 64; ++c)
            #pragma unroll
            for (int k = 0; k < 25; ++k) {
                int u = v + k - 12;
                if (u >= 0 && u < 25) acc += wk[c*25 + k] * se[c*25 + u];
            }
        g_gs[n*25 + v] = 1.0f + sigm(acc);
    }
}

// ---------------- K5: SVw = sum_v y0*(1+gs) ----------------
__global__ __launch_bounds__(256) void k5_svw() {
    __shared__ float gs[25];
    const int c = blockIdx.x, n = blockIdx.y, t = threadIdx.x;
    if (t < 25) gs[t] = g_gs[n*25 + t];
    __syncthreads();
    const float* row = &g_y0[((n*64 + c)*256 + t)*25];
    float s = 0.f;
    #pragma unroll
    for (int v = 0; v < 25; ++v) s += row[v] * gs[v];
    g_SVw[(n*64 + c)*256 + t] = s;
}

// ---------------- K6: temporal gate ----------------
__global__ __launch_bounds__(256) void k6_tgate(const float* __restrict__ Wta,
                                                const float* __restrict__ bta)
{
    __shared__ float wk[576];
    const int tid = threadIdx.x, n = blockIdx.x;
    for (int i = tid; i < 576; i += 256) wk[i] = Wta[i];
    __syncthreads();
    const int t = tid;
    float s = 0.f;
    for (int c = 0; c < 64; ++c) {
        const float* sv = &g_SVw[(n*64 + c)*256];
        #pragma unroll
        for (int k = 0; k < 9; ++k) {
            int u = t + k - 4;
            if (u >= 0 && u < 256) s += wk[c*9 + k] * sv[u];
        }
    }
    float acc = bta[0] + s * (1.0f/25.0f);
    g_gt[n*256 + t] = 1.0f + sigm(acc);
}

// ---------------- K7: channel gate ----------------
__global__ __launch_bounds__(64) void k7_cgate(
    const float* __restrict__ W1, const float* __restrict__ b1,
    const float* __restrict__ W2, const float* __restrict__ b2)
{
    __shared__ float gt[256];
    __shared__ float se[64];
    __shared__ float h[32];
    const int tid = threadIdx.x, n = blockIdx.x;
    for (int i = tid; i < 256; i += 64) gt[i] = g_gt[n*256 + i];
    __syncthreads();
    {
        const float* sv = &g_SVw[(n*64 + tid)*256];
        float s = 0.f;
        for (int t = 0; t < 256; ++t) s += sv[t] * gt[t];
        se[tid] = s * (1.0f/6400.0f);
    }
    __syncthreads();
    if (tid < 32) {
        float a = b1[tid];
        for (int c = 0; c < 64; ++c) a += W1[tid*64 + c] * se[c];
        h[tid] = fmaxf(a, 0.f);
    }
    __syncthreads();
    {
        float a = b2[tid];
        #pragma unroll
        for (int j = 0; j < 32; ++j) a += W2[tid*32 + j] * h[j];
        g_gc[n*64 + tid] = 1.0f + sigm(a);
    }
}

// ---------------- K8: finalize ----------------
__global__ __launch_bounds__(256) void k8_final(float* __restrict__ out) {
    const int i4 = blockIdx.x*256 + threadIdx.x;
    if (i4 >= NB*CC*TT*VV/4) return;
    float4 y = ((const float4*)g_y0)[i4];
    float r[4] = {y.x, y.y, y.z, y.w};
    #pragma unroll
    for (int k = 0; k < 4; ++k) {
        unsigned idx = (unsigned)i4*4u + k;
        unsigned row = idx / 25u;
        unsigned v   = idx - row*25u;
        unsigned t   = row & 255u;
        unsigned nc  = row >> 8;
        unsigned n   = nc >> 6;
        r[k] *= g_gs[n*25 + v] * g_gt[n*256 + t] * g_gc[nc];
    }
    ((float4*)out)[i4] = make_float4(r[0], r[1], r[2], r[3]);
}

// ---------------- launch ----------------
extern "C" void kernel_launch(void* const* d_in, const int* in_sizes, int n_in,
                              void* d_out, int out_size) {
    const float* x     = (const float*)d_in[0];
    const float* PA    = (const float*)d_in[1];
    const float* alpha = (const float*)d_in[2];
    const float* Wa    = (const float*)d_in[3];
    const float* ba    = (const float*)d_in[4];
    const float* Wb    = (const float*)d_in[5];
    const float* bb    = (const float*)d_in[6];
    const float* Wd    = (const float*)d_in[7];
    const float* bd    = (const float*)d_in[8];
    const float* gam   = (const float*)d_in[9];
    const float* bet   = (const float*)d_in[10];
    const float* Wsa   = (const float*)d_in[11];
    const float* bsa   = (const float*)d_in[12];
    const float* Wta   = (const float*)d_in[13];
    const float* bta   = (const float*)d_in[14];
    const float* W1    = (const float*)d_in[15];
    const float* b1    = (const float*)d_in[16];
    const float* W2    = (const float*)d_in[17];
    const float* b2    = (const float*)d_in[18];
    float* out = (float*)d_out;

    cudaFuncSetAttribute(k1_emb_adj, cudaFuncAttributeMaxDynamicSharedMemorySize, 68608);
    cudaFuncSetAttribute(k3_main,    cudaFuncAttributeMaxDynamicSharedMemorySize, 66560);

    k0_zero<<<224, 1024>>>();
    k1_emb_adj<<<dim3(8, 64), 256, 67968>>>(x, Wa, ba, Wb, bb);
    k2_adj<<<120, 1024>>>(PA, alpha);
    k3_main<<<dim3(64, 64), 128, 66304>>>(x, Wd, bd, gam, bet);
    k4_sgate<<<64, 128>>>(Wsa, bsa);
    k5_svw<<<dim3(64, 64), 256>>>();
    k6_tgate<<<64, 256>>>(Wta, bta);
    k7_cgate<<<64, 64>>>(W1, b1, W2, b2);
    k8_final<<<25600, 256>>>(out);
}